// round 12
// baseline (speedup 1.0000x reference)
#include <cuda_runtime.h>
#include <cuda_fp16.h>
#include <math.h>
#include <stdint.h>

#define NN   40000
#define NP   40064          // 313 * 128, padded
#define EE   640000
#define FIN  33
#define HH   128
#define LL   8
#define ALPHA 0.1f
#define DEGCAP 64

// ---------------- scratch (no allocation allowed) ----------------
__device__ float  g_x0[NP * HH];
__device__ float  g_xca[NP * HH];           // fp32 ping
__device__ float  g_xcb[NP * HH];           // fp32 pong
__device__ __half g_xha[NP * HH];           // fp16 scaled mirror ping
__device__ __half g_xhb[NP * HH];           // fp16 scaled mirror pong
__device__ float  g_xx[NP * HH];            // aggregation output (pad rows stay 0)
__device__ float  g_wp[LL * HH * HH];       // W' = (1-beta) I + beta W
__device__ int    g_cnt[NN];
__device__ int    g_ecol[(size_t)NN * DEGCAP];
__device__ float  g_ew[(size_t)NN * DEGCAP];

// ---------------- packed f32x2 helpers (SASS FFMA2) ----------------
__device__ __forceinline__ unsigned long long pack_dup(float v) {
    unsigned long long r;
    unsigned u = __float_as_uint(v);
    asm("mov.b64 %0, {%1, %1};" : "=l"(r) : "r"(u));
    return r;
}
__device__ __forceinline__ void fma2(unsigned long long& d, unsigned long long a,
                                     unsigned long long b) {
    asm("fma.rn.f32x2 %0, %1, %2, %3;" : "=l"(d) : "l"(a), "l"(b), "l"(d));
}
__device__ __forceinline__ void unpack2(unsigned long long v, float& lo, float& hi) {
    unsigned ul, uh;
    asm("mov.b64 {%0, %1}, %2;" : "=r"(ul), "=r"(uh) : "l"(v));
    lo = __uint_as_float(ul);
    hi = __uint_as_float(uh);
}

// ---------------- W' prep + zero cnt ----------------
__global__ void wprep_zero_kernel(const float* __restrict__ Wc) {
    int idx = blockIdx.x * blockDim.x + threadIdx.x;
    if (idx < NN) g_cnt[idx] = 0;
    if (idx < LL * HH * HH) {
        int l = idx >> 14;
        int rem = idx & 16383;
        int k = rem >> 7, n = rem & 127;
        float beta = logf(0.5f / (float)(l + 1) + 1.0f);
        float v = beta * Wc[idx];
        if (k == n) v += 1.0f - beta;
        g_wp[idx] = v;
    }
}

// ---------------- input projection: x0 = relu(x @ W_in^T + b_in) ----------------
__global__ void input_proj_kernel(const float* __restrict__ x,
                                  const float* __restrict__ Win,
                                  const float* __restrict__ bin) {
    __shared__ float sW[HH * FIN];
    __shared__ float sx[FIN];
    int tid = threadIdx.x;
    for (int i = tid; i < HH * FIN; i += 128) sW[i] = Win[i];
    float b = bin[tid];
    int row0 = blockIdx.x * 32;
    for (int r = 0; r < 32; r++) {
        int row = row0 + r;
        __syncthreads();
        if (tid < FIN) sx[tid] = x[row * FIN + tid];
        __syncthreads();
        float s = b;
#pragma unroll
        for (int f = 0; f < FIN; f++) s += sW[tid * FIN + f] * sx[f];
        s = fmaxf(s, 0.0f);
        g_x0[row * HH + tid] = s;
        g_xca[row * HH + tid] = s;
        g_xha[row * HH + tid] = __float2half_rn(s);   // scale 2^0 for layer 0
    }
}

// ---------------- ELL scatter ----------------
__global__ void scatter_ell_kernel(const int* __restrict__ er,
                                   const int* __restrict__ ec,
                                   const float* __restrict__ ew) {
    int e = blockIdx.x * blockDim.x + threadIdx.x;
    if (e < EE) {
        int r = er[e];
        int s = atomicAdd(&g_cnt[r], 1);
        if (s < DEGCAP) {
            g_ecol[(size_t)r * DEGCAP + s] = ec[e];
            g_ew[(size_t)r * DEGCAP + s] = ew[e];
        }
    }
}

// ---------------- SpMM: g_xx = invs * (A @ srcH) + 0.1 * x0 ----------------
// 2 rows per warp: 16 lanes per row, lane owns 8 fp16 feats (one LDG.128/edge).
__device__ __forceinline__ void acc8(float* a, uint4 d, float w) {
    float2 f0 = __half22float2(*(__half2*)&d.x);
    float2 f1 = __half22float2(*(((__half2*)&d.x) + 1));
    float2 f2 = __half22float2(*(__half2*)&d.z);
    float2 f3 = __half22float2(*(((__half2*)&d.z) + 1));
    a[0] += w * f0.x; a[1] += w * f0.y;
    a[2] += w * f1.x; a[3] += w * f1.y;
    a[4] += w * f2.x; a[5] += w * f2.y;
    a[6] += w * f3.x; a[7] += w * f3.y;
}

__global__ void spmm_kernel(const __half* __restrict__ srcH, float invs) {
    int gt = blockIdx.x * blockDim.x + threadIdx.x;
    int warp = gt >> 5;
    int lane = threadIdx.x & 31;
    int hsel = lane >> 4;          // which of the 2 rows
    int hl = lane & 15;            // feature group: 8 halfs at hl*8
    int row = warp * 2 + hsel;
    if (row >= NN) return;
    int cn = g_cnt[row];
    cn = cn < DEGCAP ? cn : DEGCAP;
    const int* cb = g_ecol + (size_t)row * DEGCAP;
    const float* wb = g_ew + (size_t)row * DEGCAP;

    float aA[8] = {0.f, 0.f, 0.f, 0.f, 0.f, 0.f, 0.f, 0.f};
    float aB[8] = {0.f, 0.f, 0.f, 0.f, 0.f, 0.f, 0.f, 0.f};
    int fo = hl * 8;
    int i = 0;
    for (; i + 4 <= cn; i += 4) {
        int4 c = *(const int4*)&cb[i];
        float4 w = *(const float4*)&wb[i];
        uint4 d0 = *(const uint4*)&srcH[(size_t)c.x * HH + fo];
        uint4 d1 = *(const uint4*)&srcH[(size_t)c.y * HH + fo];
        uint4 d2 = *(const uint4*)&srcH[(size_t)c.z * HH + fo];
        uint4 d3 = *(const uint4*)&srcH[(size_t)c.w * HH + fo];
        acc8(aA, d0, w.x);
        acc8(aB, d1, w.y);
        acc8(aA, d2, w.z);
        acc8(aB, d3, w.w);
    }
    for (; i < cn; i++) {
        int c = cb[i];
        float w = wb[i];
        uint4 d = *(const uint4*)&srcH[(size_t)c * HH + fo];
        acc8(aA, d, w);
    }
#pragma unroll
    for (int j = 0; j < 8; j++) aA[j] += aB[j];

    const float* x0p = &g_x0[(size_t)row * HH + fo];
    float4 x00 = *(const float4*)x0p;
    float4 x01 = *(const float4*)(x0p + 4);
    float4 o0, o1;
    o0.x = invs * aA[0] + ALPHA * x00.x;
    o0.y = invs * aA[1] + ALPHA * x00.y;
    o0.z = invs * aA[2] + ALPHA * x00.z;
    o0.w = invs * aA[3] + ALPHA * x00.w;
    o1.x = invs * aA[4] + ALPHA * x01.x;
    o1.y = invs * aA[5] + ALPHA * x01.y;
    o1.z = invs * aA[6] + ALPHA * x01.z;
    o1.w = invs * aA[7] + ALPHA * x01.w;
    float* xxp = &g_xx[(size_t)row * HH + fo];
    *(float4*)xxp = o0;
    *(float4*)(xxp + 4) = o1;
}

// ---------------- GEMM (FFMA2): dst = src + relu(g_xx @ W'); fp16 mirror ---------
// BM=128, BN=128, BK=16, 256 threads = 8 warps (4m x 2n).
// Thread tile 8m x 8n: 4 f32x2 m-pairs x 8 n => 32 FFMA2 per k,
// fed by 2 LDS.128 (A, 64B unique/warp) + 2 LDS.128 (B, 128B unique/warp).
__global__ void __launch_bounds__(256) gemm_kernel(const float* __restrict__ src,
                                                   float* __restrict__ dst,
                                                   __half* __restrict__ dstH,
                                                   const float* __restrict__ Wp,
                                                   float hscale) {
    __shared__ float As[16][132];
    __shared__ float Bs[16][132];
    int tid = threadIdx.x;
    int wid = tid >> 5, lane = tid & 31;
    int wm = wid >> 1, wn = wid & 1;
    int lane_r = (lane >> 3);
    int lane_c = lane & 7;
    int mt = wm * 32 + lane_r * 8;          // first of 8 consecutive rows
    int nt = wn * 64 + lane_c * 8;          // first of 8 consecutive cols
    int r0 = blockIdx.x * 128;
    const float* Ag = g_xx + (size_t)r0 * HH;

    unsigned long long acc2[4][8];
#pragma unroll
    for (int p = 0; p < 4; p++)
#pragma unroll
        for (int n = 0; n < 8; n++) acc2[p][n] = 0ULL;

#pragma unroll 1
    for (int c = 0; c < 8; c++) {
        // load A chunk: 128 m x 16 k, transpose to As[k][m]
#pragma unroll
        for (int i = 0; i < 2; i++) {
            int idx = tid + i * 256;        // 0..511
            int m = idx >> 2, kq = idx & 3;
            float4 v = *(const float4*)&Ag[m * HH + c * 16 + kq * 4];
            As[kq * 4 + 0][m] = v.x;
            As[kq * 4 + 1][m] = v.y;
            As[kq * 4 + 2][m] = v.z;
            As[kq * 4 + 3][m] = v.w;
        }
        // load B chunk: 16 k x 128 n, natural layout
#pragma unroll
        for (int i = 0; i < 2; i++) {
            int idx = tid + i * 256;
            int k = idx >> 5, n4 = idx & 31;
            *(float4*)&Bs[k][n4 * 4] = *(const float4*)&Wp[(c * 16 + k) * HH + n4 * 4];
        }
        __syncthreads();
#pragma unroll
        for (int k = 0; k < 16; k++) {
            ulonglong2 aA = *(const ulonglong2*)&As[k][mt];       // m-pairs 0,1
            ulonglong2 aB = *(const ulonglong2*)&As[k][mt + 4];   // m-pairs 2,3
            float4 b0 = *(const float4*)&Bs[k][nt];
            float4 b1 = *(const float4*)&Bs[k][nt + 4];
            unsigned long long bd;
            bd = pack_dup(b0.x);
            fma2(acc2[0][0], aA.x, bd); fma2(acc2[1][0], aA.y, bd);
            fma2(acc2[2][0], aB.x, bd); fma2(acc2[3][0], aB.y, bd);
            bd = pack_dup(b0.y);
            fma2(acc2[0][1], aA.x, bd); fma2(acc2[1][1], aA.y, bd);
            fma2(acc2[2][1], aB.x, bd); fma2(acc2[3][1], aB.y, bd);
            bd = pack_dup(b0.z);
            fma2(acc2[0][2], aA.x, bd); fma2(acc2[1][2], aA.y, bd);
            fma2(acc2[2][2], aB.x, bd); fma2(acc2[3][2], aB.y, bd);
            bd = pack_dup(b0.w);
            fma2(acc2[0][3], aA.x, bd); fma2(acc2[1][3], aA.y, bd);
            fma2(acc2[2][3], aB.x, bd); fma2(acc2[3][3], aB.y, bd);
            bd = pack_dup(b1.x);
            fma2(acc2[0][4], aA.x, bd); fma2(acc2[1][4], aA.y, bd);
            fma2(acc2[2][4], aB.x, bd); fma2(acc2[3][4], aB.y, bd);
            bd = pack_dup(b1.y);
            fma2(acc2[0][5], aA.x, bd); fma2(acc2[1][5], aA.y, bd);
            fma2(acc2[2][5], aB.x, bd); fma2(acc2[3][5], aB.y, bd);
            bd = pack_dup(b1.z);
            fma2(acc2[0][6], aA.x, bd); fma2(acc2[1][6], aA.y, bd);
            fma2(acc2[2][6], aB.x, bd); fma2(acc2[3][6], aB.y, bd);
            bd = pack_dup(b1.w);
            fma2(acc2[0][7], aA.x, bd); fma2(acc2[1][7], aA.y, bd);
            fma2(acc2[2][7], aB.x, bd); fma2(acc2[3][7], aB.y, bd);
        }
        __syncthreads();
    }

    // epilogue: pair p covers rows mt + 2p (lo) and mt + 2p + 1 (hi)
#pragma unroll
    for (int p = 0; p < 4; p++) {
        float lo[8], hi[8];
#pragma unroll
        for (int n = 0; n < 8; n++) unpack2(acc2[p][n], lo[n], hi[n]);
#pragma unroll
        for (int h = 0; h < 2; h++) {
            int row = r0 + mt + 2 * p + h;
            const float* vv = h ? hi : lo;
            const float* srp = &src[(size_t)row * HH + nt];
            float4 cv0 = *(const float4*)srp;
            float4 cv1 = *(const float4*)(srp + 4);
            cv0.x += fmaxf(vv[0], 0.f);
            cv0.y += fmaxf(vv[1], 0.f);
            cv0.z += fmaxf(vv[2], 0.f);
            cv0.w += fmaxf(vv[3], 0.f);
            cv1.x += fmaxf(vv[4], 0.f);
            cv1.y += fmaxf(vv[5], 0.f);
            cv1.z += fmaxf(vv[6], 0.f);
            cv1.w += fmaxf(vv[7], 0.f);
            float* dsp = &dst[(size_t)row * HH + nt];
            *(float4*)dsp = cv0;
            *(float4*)(dsp + 4) = cv1;
            __half2 h0 = __floats2half2_rn(cv0.x * hscale, cv0.y * hscale);
            __half2 h1 = __floats2half2_rn(cv0.z * hscale, cv0.w * hscale);
            __half2 h2 = __floats2half2_rn(cv1.x * hscale, cv1.y * hscale);
            __half2 h3 = __floats2half2_rn(cv1.z * hscale, cv1.w * hscale);
            uint4 hp;
            hp.x = *(const unsigned*)&h0;
            hp.y = *(const unsigned*)&h1;
            hp.z = *(const unsigned*)&h2;
            hp.w = *(const unsigned*)&h3;
            *(uint4*)&dstH[(size_t)row * HH + nt] = hp;
        }
    }
}

// ---------------- output projection: out = xc @ W_out^T + b_out ----------------
__global__ void out_proj_kernel(const float* __restrict__ xc,
                                const float* __restrict__ Wout,
                                const float* __restrict__ bout,
                                float* __restrict__ out) {
    int gt = blockIdx.x * blockDim.x + threadIdx.x;
    int row = gt >> 5;
    int lane = threadIdx.x & 31;
    if (row >= NN) return;
    float4 v = ((const float4*)xc)[row * 32 + lane];
#pragma unroll
    for (int c = 0; c < 3; c++) {
        float4 w = *(const float4*)&Wout[c * HH + lane * 4];
        float s = v.x * w.x + v.y * w.y + v.z * w.z + v.w * w.w;
#pragma unroll
        for (int o = 16; o; o >>= 1) s += __shfl_down_sync(0xFFFFFFFFu, s, o);
        if (lane == 0) out[row * 3 + c] = s + bout[c];
    }
}

extern "C" void kernel_launch(void* const* d_in, const int* in_sizes, int n_in,
                              void* d_out, int out_size) {
    const float* x    = (const float*)d_in[0];
    const int*   er   = (const int*)d_in[1];
    const int*   ec   = (const int*)d_in[2];
    const float* ew   = (const float*)d_in[3];
    const float* Win  = (const float*)d_in[4];
    const float* bin  = (const float*)d_in[5];
    const float* Wout = (const float*)d_in[6];
    const float* bout = (const float*)d_in[7];
    const float* Wc   = (const float*)d_in[8];
    float* out = (float*)d_out;

    float*  bufA; cudaGetSymbolAddress((void**)&bufA, g_xca);
    float*  bufB; cudaGetSymbolAddress((void**)&bufB, g_xcb);
    __half* hbufA; cudaGetSymbolAddress((void**)&hbufA, g_xha);
    __half* hbufB; cudaGetSymbolAddress((void**)&hbufB, g_xhb);
    float*  wp;   cudaGetSymbolAddress((void**)&wp, g_wp);

    wprep_zero_kernel<<<(LL * HH * HH + 255) / 256, 256>>>(Wc);
    input_proj_kernel<<<NN / 32, 128>>>(x, Win, bin);
    scatter_ell_kernel<<<(EE + 255) / 256, 256>>>(er, ec, ew);

    for (int l = 0; l < LL; l++) {
        const float*  src  = (l & 1) ? bufB : bufA;
        float*        dst  = (l & 1) ? bufA : bufB;
        const __half* srcH = (l & 1) ? hbufB : hbufA;
        __half*       dstH = (l & 1) ? hbufA : hbufB;
        float invs = ldexpf(0.9f, 3 * l);            // 0.9 * 2^{3l}
        float hscale = ldexpf(1.0f, -3 * (l + 1));   // 2^{-3(l+1)}
        spmm_kernel<<<(NN / 2 * 32 + 255) / 256, 256>>>(srcH, invs);
        gemm_kernel<<<NP / 128, 256>>>(src, dst, dstH,
                                       wp + (size_t)l * HH * HH, hscale);
    }

    out_proj_kernel<<<(NN * 32 + 255) / 256, 256>>>(bufA, Wout, bout, out);
}

// round 13
// speedup vs baseline: 1.2908x; 1.2908x over previous
#include <cuda_runtime.h>
#include <cuda_fp16.h>
#include <math.h>
#include <stdint.h>

#define NN   40000
#define NP   40064          // 313 * 128, padded
#define EE   640000
#define FIN  33
#define HH   128
#define LL   8
#define ALPHA 0.1f
#define DEGCAP 64

// ---------------- scratch (no allocation allowed) ----------------
__device__ float  g_x0[NP * HH];
__device__ float  g_xca[NP * HH];           // fp32 ping
__device__ float  g_xcb[NP * HH];           // fp32 pong
__device__ __half g_xha[NP * HH];           // fp16 scaled mirror ping
__device__ __half g_xhb[NP * HH];           // fp16 scaled mirror pong
__device__ float  g_xx[NP * HH];            // aggregation output (pad rows stay 0)
__device__ float  g_wp[LL * HH * HH];       // W' = (1-beta) I + beta W
__device__ int    g_cnt[NN];
__device__ int    g_ecol[(size_t)NN * DEGCAP];
__device__ float  g_ew[(size_t)NN * DEGCAP];

// ---------------- packed f32x2 helpers (SASS FFMA2) ----------------
__device__ __forceinline__ unsigned long long pack_dup(float v) {
    unsigned long long r;
    unsigned u = __float_as_uint(v);
    asm("mov.b64 %0, {%1, %1};" : "=l"(r) : "r"(u));
    return r;
}
__device__ __forceinline__ void fma2(unsigned long long& d, unsigned long long a,
                                     unsigned long long b) {
    asm("fma.rn.f32x2 %0, %1, %2, %3;" : "=l"(d) : "l"(a), "l"(b), "l"(d));
}
__device__ __forceinline__ void unpack2(unsigned long long v, float& lo, float& hi) {
    unsigned ul, uh;
    asm("mov.b64 {%0, %1}, %2;" : "=r"(ul), "=r"(uh) : "l"(v));
    lo = __uint_as_float(ul);
    hi = __uint_as_float(uh);
}

// ---------------- launch 0: zero cnt ----------------
__global__ void zero_cnt_kernel() {
    int i = blockIdx.x * blockDim.x + threadIdx.x;
    if (i < NN) g_cnt[i] = 0;
}

// ---------------- launch 1: W' = beta*W + (1-beta)*I ----------------
__global__ void wprep_kernel(const float* __restrict__ Wc) {
    int idx = blockIdx.x * blockDim.x + threadIdx.x;
    if (idx >= LL * HH * HH) return;
    int l = idx >> 14;
    int rem = idx & 16383;
    int k = rem >> 7, n = rem & 127;
    float beta = logf(0.5f / (float)(l + 1) + 1.0f);
    float v = beta * Wc[idx];
    if (k == n) v += 1.0f - beta;
    g_wp[idx] = v;
}

// ---------------- launch 2: input projection ----------------
__global__ void input_proj_kernel(const float* __restrict__ x,
                                  const float* __restrict__ Win,
                                  const float* __restrict__ bin) {
    __shared__ float sW[HH * FIN];
    __shared__ float sx[FIN];
    int tid = threadIdx.x;
    for (int i = tid; i < HH * FIN; i += 128) sW[i] = Win[i];
    float b = bin[tid];
    int row0 = blockIdx.x * 32;
    for (int r = 0; r < 32; r++) {
        int row = row0 + r;
        __syncthreads();
        if (tid < FIN) sx[tid] = x[row * FIN + tid];
        __syncthreads();
        float s = b;
#pragma unroll
        for (int f = 0; f < FIN; f++) s += sW[tid * FIN + f] * sx[f];
        s = fmaxf(s, 0.0f);
        g_x0[row * HH + tid] = s;
        g_xca[row * HH + tid] = s;
        g_xha[row * HH + tid] = __float2half_rn(s);   // scale 2^0 for layer 0
    }
}

// ---------------- launch 3: ELL scatter ----------------
__global__ void scatter_ell_kernel(const int* __restrict__ er,
                                   const int* __restrict__ ec,
                                   const float* __restrict__ ew) {
    int e = blockIdx.x * blockDim.x + threadIdx.x;
    if (e < EE) {
        int r = er[e];
        int s = atomicAdd(&g_cnt[r], 1);
        if (s < DEGCAP) {
            g_ecol[(size_t)r * DEGCAP + s] = ec[e];
            g_ew[(size_t)r * DEGCAP + s] = ew[e];
        }
    }
}

// ---------------- SpMM: g_xx = invs * (A @ srcH) + 0.1 * x0 ----------------
// 2 rows per warp: 16 lanes per row, lane owns 8 fp16 feats (one LDG.128/edge).
__device__ __forceinline__ void acc8(float* a, uint4 d, float w) {
    float2 f0 = __half22float2(*(__half2*)&d.x);
    float2 f1 = __half22float2(*(((__half2*)&d.x) + 1));
    float2 f2 = __half22float2(*(__half2*)&d.z);
    float2 f3 = __half22float2(*(((__half2*)&d.z) + 1));
    a[0] += w * f0.x; a[1] += w * f0.y;
    a[2] += w * f1.x; a[3] += w * f1.y;
    a[4] += w * f2.x; a[5] += w * f2.y;
    a[6] += w * f3.x; a[7] += w * f3.y;
}

__global__ void spmm_kernel(const __half* __restrict__ srcH, float invs) {
    int gt = blockIdx.x * blockDim.x + threadIdx.x;
    int warp = gt >> 5;
    int lane = threadIdx.x & 31;
    int hsel = lane >> 4;          // which of the 2 rows
    int hl = lane & 15;            // feature group: 8 halfs at hl*8
    int row = warp * 2 + hsel;
    if (row >= NN) return;
    int cn = g_cnt[row];
    cn = cn < DEGCAP ? cn : DEGCAP;
    const int* cb = g_ecol + (size_t)row * DEGCAP;
    const float* wb = g_ew + (size_t)row * DEGCAP;

    float aA[8] = {0.f, 0.f, 0.f, 0.f, 0.f, 0.f, 0.f, 0.f};
    float aB[8] = {0.f, 0.f, 0.f, 0.f, 0.f, 0.f, 0.f, 0.f};
    int fo = hl * 8;
    int i = 0;
    for (; i + 4 <= cn; i += 4) {
        int4 c = *(const int4*)&cb[i];
        float4 w = *(const float4*)&wb[i];
        uint4 d0 = *(const uint4*)&srcH[(size_t)c.x * HH + fo];
        uint4 d1 = *(const uint4*)&srcH[(size_t)c.y * HH + fo];
        uint4 d2 = *(const uint4*)&srcH[(size_t)c.z * HH + fo];
        uint4 d3 = *(const uint4*)&srcH[(size_t)c.w * HH + fo];
        acc8(aA, d0, w.x);
        acc8(aB, d1, w.y);
        acc8(aA, d2, w.z);
        acc8(aB, d3, w.w);
    }
    for (; i < cn; i++) {
        int c = cb[i];
        float w = wb[i];
        uint4 d = *(const uint4*)&srcH[(size_t)c * HH + fo];
        acc8(aA, d, w);
    }
#pragma unroll
    for (int j = 0; j < 8; j++) aA[j] += aB[j];

    const float* x0p = &g_x0[(size_t)row * HH + fo];
    float4 x00 = *(const float4*)x0p;
    float4 x01 = *(const float4*)(x0p + 4);
    float4 o0, o1;
    o0.x = invs * aA[0] + ALPHA * x00.x;
    o0.y = invs * aA[1] + ALPHA * x00.y;
    o0.z = invs * aA[2] + ALPHA * x00.z;
    o0.w = invs * aA[3] + ALPHA * x00.w;
    o1.x = invs * aA[4] + ALPHA * x01.x;
    o1.y = invs * aA[5] + ALPHA * x01.y;
    o1.z = invs * aA[6] + ALPHA * x01.z;
    o1.w = invs * aA[7] + ALPHA * x01.w;
    float* xxp = &g_xx[(size_t)row * HH + fo];
    *(float4*)xxp = o0;
    *(float4*)(xxp + 4) = o1;
}

// ---------------- GEMM (FFMA2, double-buffered): dst = src + relu(g_xx @ W') -----
// BM=64, BN=128, BK=16, 256 threads; warp = 8 rows (A broadcast), lane = 4 cols.
// acc 4 m-pairs x 4 n packed f32x2. Register-staged prefetch, 1 sync per chunk.
__global__ void __launch_bounds__(256) gemm_kernel(const float* __restrict__ src,
                                                   float* __restrict__ dst,
                                                   __half* __restrict__ dstH,
                                                   const float* __restrict__ Wp,
                                                   float hscale) {
    __shared__ float As[2][16][68];
    __shared__ float Bs[2][16][128];
    int tid = threadIdx.x;
    int tx = tid & 31;
    int ty = tid >> 5;
    int r0 = blockIdx.x * 64;
    const float* Ag = g_xx + (size_t)r0 * HH;

    int m_ld = tid >> 2, kq = tid & 3;       // A loader coords
    int bk0 = tid >> 4, bc0 = (tid & 15) * 2; // B loader: k=tid>>4, two float4 cols

    unsigned long long acc2[4][4];
#pragma unroll
    for (int p = 0; p < 4; p++)
#pragma unroll
        for (int c = 0; c < 4; c++) acc2[p][c] = 0ULL;

    // prime chunk 0
    {
        float4 vA = *(const float4*)&Ag[m_ld * HH + kq * 4];
        As[0][kq * 4 + 0][m_ld] = vA.x;
        As[0][kq * 4 + 1][m_ld] = vA.y;
        As[0][kq * 4 + 2][m_ld] = vA.z;
        As[0][kq * 4 + 3][m_ld] = vA.w;
        float4 vB0 = *(const float4*)&Wp[bk0 * HH + bc0 * 4];
        float4 vB1 = *(const float4*)&Wp[bk0 * HH + bc0 * 4 + 4];
        *(float4*)&Bs[0][bk0][bc0 * 4] = vB0;
        *(float4*)&Bs[0][bk0][bc0 * 4 + 4] = vB1;
    }
    __syncthreads();

#pragma unroll
    for (int c = 0; c < 8; c++) {
        int cur = c & 1;
        float4 pA, pB0, pB1;
        if (c < 7) {
            const float* Agn = Ag + (c + 1) * 16;
            const float* Wpn = Wp + (c + 1) * 16 * HH;
            pA = *(const float4*)&Agn[m_ld * HH + kq * 4];
            pB0 = *(const float4*)&Wpn[bk0 * HH + bc0 * 4];
            pB1 = *(const float4*)&Wpn[bk0 * HH + bc0 * 4 + 4];
        }
#pragma unroll
        for (int k = 0; k < 16; k++) {
            ulonglong2 a01 = *(const ulonglong2*)&As[cur][k][ty * 8];
            ulonglong2 a23 = *(const ulonglong2*)&As[cur][k][ty * 8 + 4];
            float4 bb = *(const float4*)&Bs[cur][k][tx * 4];
            unsigned long long bd0 = pack_dup(bb.x);
            unsigned long long bd1 = pack_dup(bb.y);
            unsigned long long bd2 = pack_dup(bb.z);
            unsigned long long bd3 = pack_dup(bb.w);
            fma2(acc2[0][0], a01.x, bd0); fma2(acc2[0][1], a01.x, bd1);
            fma2(acc2[0][2], a01.x, bd2); fma2(acc2[0][3], a01.x, bd3);
            fma2(acc2[1][0], a01.y, bd0); fma2(acc2[1][1], a01.y, bd1);
            fma2(acc2[1][2], a01.y, bd2); fma2(acc2[1][3], a01.y, bd3);
            fma2(acc2[2][0], a23.x, bd0); fma2(acc2[2][1], a23.x, bd1);
            fma2(acc2[2][2], a23.x, bd2); fma2(acc2[2][3], a23.x, bd3);
            fma2(acc2[3][0], a23.y, bd0); fma2(acc2[3][1], a23.y, bd1);
            fma2(acc2[3][2], a23.y, bd2); fma2(acc2[3][3], a23.y, bd3);
        }
        if (c < 7) {
            int nxt = cur ^ 1;
            As[nxt][kq * 4 + 0][m_ld] = pA.x;
            As[nxt][kq * 4 + 1][m_ld] = pA.y;
            As[nxt][kq * 4 + 2][m_ld] = pA.z;
            As[nxt][kq * 4 + 3][m_ld] = pA.w;
            *(float4*)&Bs[nxt][bk0][bc0 * 4] = pB0;
            *(float4*)&Bs[nxt][bk0][bc0 * 4 + 4] = pB1;
            __syncthreads();
        }
    }

    // epilogue: pair p holds rows (2p, 2p+1) of this thread's 8-row group
#pragma unroll
    for (int p = 0; p < 4; p++) {
        float lo0, hi0, lo1, hi1, lo2, hi2, lo3, hi3;
        unpack2(acc2[p][0], lo0, hi0);
        unpack2(acc2[p][1], lo1, hi1);
        unpack2(acc2[p][2], lo2, hi2);
        unpack2(acc2[p][3], lo3, hi3);
        int rowe = r0 + ty * 8 + 2 * p;
#pragma unroll
        for (int h = 0; h < 2; h++) {
            int row = rowe + h;
            float v0 = h ? hi0 : lo0;
            float v1 = h ? hi1 : lo1;
            float v2 = h ? hi2 : lo2;
            float v3 = h ? hi3 : lo3;
            const float* srp = &src[(size_t)row * HH + tx * 4];
            float4 cv = *(const float4*)srp;
            cv.x += fmaxf(v0, 0.f);
            cv.y += fmaxf(v1, 0.f);
            cv.z += fmaxf(v2, 0.f);
            cv.w += fmaxf(v3, 0.f);
            *(float4*)&dst[(size_t)row * HH + tx * 4] = cv;
            __half2 h0 = __floats2half2_rn(cv.x * hscale, cv.y * hscale);
            __half2 h1 = __floats2half2_rn(cv.z * hscale, cv.w * hscale);
            uint2 hp;
            hp.x = *(const unsigned*)&h0;
            hp.y = *(const unsigned*)&h1;
            *(uint2*)&dstH[(size_t)row * HH + tx * 4] = hp;
        }
    }
}

// ---------------- output projection: out = xc @ W_out^T + b_out ----------------
__global__ void out_proj_kernel(const float* __restrict__ xc,
                                const float* __restrict__ Wout,
                                const float* __restrict__ bout,
                                float* __restrict__ out) {
    int gt = blockIdx.x * blockDim.x + threadIdx.x;
    int row = gt >> 5;
    int lane = threadIdx.x & 31;
    if (row >= NN) return;
    float4 v = ((const float4*)xc)[row * 32 + lane];
#pragma unroll
    for (int c = 0; c < 3; c++) {
        float4 w = *(const float4*)&Wout[c * HH + lane * 4];
        float s = v.x * w.x + v.y * w.y + v.z * w.z + v.w * w.w;
#pragma unroll
        for (int o = 16; o; o >>= 1) s += __shfl_down_sync(0xFFFFFFFFu, s, o);
        if (lane == 0) out[row * 3 + c] = s + bout[c];
    }
}

extern "C" void kernel_launch(void* const* d_in, const int* in_sizes, int n_in,
                              void* d_out, int out_size) {
    const float* x    = (const float*)d_in[0];
    const int*   er   = (const int*)d_in[1];
    const int*   ec   = (const int*)d_in[2];
    const float* ew   = (const float*)d_in[3];
    const float* Win  = (const float*)d_in[4];
    const float* bin  = (const float*)d_in[5];
    const float* Wout = (const float*)d_in[6];
    const float* bout = (const float*)d_in[7];
    const float* Wc   = (const float*)d_in[8];
    float* out = (float*)d_out;

    float*  bufA; cudaGetSymbolAddress((void**)&bufA, g_xca);
    float*  bufB; cudaGetSymbolAddress((void**)&bufB, g_xcb);
    __half* hbufA; cudaGetSymbolAddress((void**)&hbufA, g_xha);
    __half* hbufB; cudaGetSymbolAddress((void**)&hbufB, g_xhb);
    float*  wp;   cudaGetSymbolAddress((void**)&wp, g_wp);

    zero_cnt_kernel<<<(NN + 255) / 256, 256>>>();                    // launch 0
    wprep_kernel<<<(LL * HH * HH + 255) / 256, 256>>>(Wc);           // launch 1
    input_proj_kernel<<<NN / 32, 128>>>(x, Win, bin);                // launch 2
    scatter_ell_kernel<<<(EE + 255) / 256, 256>>>(er, ec, ew);       // launch 3

    for (int l = 0; l < LL; l++) {
        const float*  src  = (l & 1) ? bufB : bufA;
        float*        dst  = (l & 1) ? bufA : bufB;
        const __half* srcH = (l & 1) ? hbufB : hbufA;
        __half*       dstH = (l & 1) ? hbufA : hbufB;
        float invs = ldexpf(0.9f, 3 * l);            // 0.9 * 2^{3l}
        float hscale = ldexpf(1.0f, -3 * (l + 1));   // 2^{-3(l+1)}
        spmm_kernel<<<(NN / 2 * 32 + 255) / 256, 256>>>(srcH, invs); // launch 4 on l=0
        gemm_kernel<<<NP / 64, 256>>>(src, dst, dstH,                // launch 5 on l=0
                                      wp + (size_t)l * HH * HH, hscale);
    }

    out_proj_kernel<<<(NN * 32 + 255) / 256, 256>>>(bufA, Wout, bout, out);
}

// round 14
// speedup vs baseline: 1.3776x; 1.0672x over previous
#include <cuda_runtime.h>
#include <cuda_fp16.h>
#include <math.h>
#include <stdint.h>

#define NN   40000
#define NP   40064          // 313 * 128, padded
#define EE   640000
#define FIN  33
#define HH   128
#define LL   8
#define ALPHA 0.1f
#define DEGCAP 64

// ---------------- scratch (no allocation allowed) ----------------
__device__ float  g_x0[NP * HH];
__device__ float  g_xca[NP * HH];           // fp32 ping
__device__ float  g_xcb[NP * HH];           // fp32 pong
__device__ __half g_xha[NP * HH];           // fp16 scaled xc mirror ping
__device__ __half g_xhb[NP * HH];           // fp16 scaled xc mirror pong
__device__ float  g_xx[NP * HH];            // aggregation output fp32
__device__ __half g_xxh[NP * HH];           // aggregation output fp16 (scaled)
__device__ __half g_wh[LL * HH * HH];       // W^T fp16: [l][n][k]
__device__ int    g_cnt[NN];
__device__ int    g_ecol[(size_t)NN * DEGCAP];
__device__ float  g_ew[(size_t)NN * DEGCAP];

// ---------------- launch 0: zero cnt ----------------
__global__ void zero_cnt_kernel() {
    int i = blockIdx.x * blockDim.x + threadIdx.x;
    if (i < NN) g_cnt[i] = 0;
}

// ---------------- launch 1: Wh = fp16(W^T) per layer ----------------
__global__ void whprep_kernel(const float* __restrict__ Wc) {
    int idx = blockIdx.x * blockDim.x + threadIdx.x;
    if (idx >= LL * HH * HH) return;
    int l = idx >> 14;
    int rem = idx & 16383;
    int n = rem >> 7, k = rem & 127;
    g_wh[idx] = __float2half_rn(Wc[(l << 14) + k * HH + n]);
}

// ---------------- launch 2: input projection ----------------
__global__ void input_proj_kernel(const float* __restrict__ x,
                                  const float* __restrict__ Win,
                                  const float* __restrict__ bin) {
    __shared__ float sW[HH * FIN];
    __shared__ float sx[FIN];
    int tid = threadIdx.x;
    for (int i = tid; i < HH * FIN; i += 128) sW[i] = Win[i];
    float b = bin[tid];
    int row0 = blockIdx.x * 32;
    for (int r = 0; r < 32; r++) {
        int row = row0 + r;
        __syncthreads();
        if (tid < FIN) sx[tid] = x[row * FIN + tid];
        __syncthreads();
        float s = b;
#pragma unroll
        for (int f = 0; f < FIN; f++) s += sW[tid * FIN + f] * sx[f];
        s = fmaxf(s, 0.0f);
        g_x0[row * HH + tid] = s;
        g_xca[row * HH + tid] = s;
        g_xha[row * HH + tid] = __float2half_rn(s);   // scale 2^0 for layer 0
    }
}

// ---------------- launch 3: ELL scatter ----------------
__global__ void scatter_ell_kernel(const int* __restrict__ er,
                                   const int* __restrict__ ec,
                                   const float* __restrict__ ew) {
    int e = blockIdx.x * blockDim.x + threadIdx.x;
    if (e < EE) {
        int r = er[e];
        int s = atomicAdd(&g_cnt[r], 1);
        if (s < DEGCAP) {
            g_ecol[(size_t)r * DEGCAP + s] = ec[e];
            g_ew[(size_t)r * DEGCAP + s] = ew[e];
        }
    }
}

// ---------------- SpMM: g_xx = invs*(A @ srcH) + 0.1*x0 ; g_xxh = g_xx * sxx ----
// 2 rows per warp: 16 lanes per row, lane owns 8 fp16 feats (one LDG.128/edge).
__device__ __forceinline__ void acc8(float* a, uint4 d, float w) {
    float2 f0 = __half22float2(*(__half2*)&d.x);
    float2 f1 = __half22float2(*(((__half2*)&d.x) + 1));
    float2 f2 = __half22float2(*(__half2*)&d.z);
    float2 f3 = __half22float2(*(((__half2*)&d.z) + 1));
    a[0] += w * f0.x; a[1] += w * f0.y;
    a[2] += w * f1.x; a[3] += w * f1.y;
    a[4] += w * f2.x; a[5] += w * f2.y;
    a[6] += w * f3.x; a[7] += w * f3.y;
}

__global__ void spmm_kernel(const __half* __restrict__ srcH, float invs, float sxx) {
    int gt = blockIdx.x * blockDim.x + threadIdx.x;
    int warp = gt >> 5;
    int lane = threadIdx.x & 31;
    int hsel = lane >> 4;
    int hl = lane & 15;
    int row = warp * 2 + hsel;
    if (row >= NN) return;
    int cn = g_cnt[row];
    cn = cn < DEGCAP ? cn : DEGCAP;
    const int* cb = g_ecol + (size_t)row * DEGCAP;
    const float* wb = g_ew + (size_t)row * DEGCAP;

    float aA[8] = {0.f, 0.f, 0.f, 0.f, 0.f, 0.f, 0.f, 0.f};
    float aB[8] = {0.f, 0.f, 0.f, 0.f, 0.f, 0.f, 0.f, 0.f};
    int fo = hl * 8;
    int i = 0;
    for (; i + 4 <= cn; i += 4) {
        int4 c = *(const int4*)&cb[i];
        float4 w = *(const float4*)&wb[i];
        uint4 d0 = *(const uint4*)&srcH[(size_t)c.x * HH + fo];
        uint4 d1 = *(const uint4*)&srcH[(size_t)c.y * HH + fo];
        uint4 d2 = *(const uint4*)&srcH[(size_t)c.z * HH + fo];
        uint4 d3 = *(const uint4*)&srcH[(size_t)c.w * HH + fo];
        acc8(aA, d0, w.x);
        acc8(aB, d1, w.y);
        acc8(aA, d2, w.z);
        acc8(aB, d3, w.w);
    }
    for (; i < cn; i++) {
        int c = cb[i];
        float w = wb[i];
        uint4 d = *(const uint4*)&srcH[(size_t)c * HH + fo];
        acc8(aA, d, w);
    }
#pragma unroll
    for (int j = 0; j < 8; j++) aA[j] += aB[j];

    const float* x0p = &g_x0[(size_t)row * HH + fo];
    float4 x00 = *(const float4*)x0p;
    float4 x01 = *(const float4*)(x0p + 4);
    float o[8];
    o[0] = invs * aA[0] + ALPHA * x00.x;
    o[1] = invs * aA[1] + ALPHA * x00.y;
    o[2] = invs * aA[2] + ALPHA * x00.z;
    o[3] = invs * aA[3] + ALPHA * x00.w;
    o[4] = invs * aA[4] + ALPHA * x01.x;
    o[5] = invs * aA[5] + ALPHA * x01.y;
    o[6] = invs * aA[6] + ALPHA * x01.z;
    o[7] = invs * aA[7] + ALPHA * x01.w;
    float* xxp = &g_xx[(size_t)row * HH + fo];
    *(float4*)xxp = make_float4(o[0], o[1], o[2], o[3]);
    *(float4*)(xxp + 4) = make_float4(o[4], o[5], o[6], o[7]);
    __half2 h0 = __floats2half2_rn(o[0] * sxx, o[1] * sxx);
    __half2 h1 = __floats2half2_rn(o[2] * sxx, o[3] * sxx);
    __half2 h2 = __floats2half2_rn(o[4] * sxx, o[5] * sxx);
    __half2 h3 = __floats2half2_rn(o[6] * sxx, o[7] * sxx);
    uint4 hp;
    hp.x = *(const unsigned*)&h0;
    hp.y = *(const unsigned*)&h1;
    hp.z = *(const unsigned*)&h2;
    hp.w = *(const unsigned*)&h3;
    *(uint4*)&g_xxh[(size_t)row * HH + fo] = hp;
}

// ---------------- GEMM (HMMA m16n8k16): out = (1-b)*xx + b*(xx@W); residual -----
// CTA 128x128x128, 8 warps (4m x 2n), warp tile 32x64.
// smem stride 136 halfs => conflict-free fragment loads (bank = qid*4 + qt).
#define MSTR 136
#define SMEM_MMA (2 * 128 * MSTR * 2)

__device__ __forceinline__ void hmma(float* d, const uint32_t* a,
                                     uint32_t b0, uint32_t b1) {
    asm volatile(
        "mma.sync.aligned.m16n8k16.row.col.f32.f16.f16.f32 "
        "{%0,%1,%2,%3}, {%4,%5,%6,%7}, {%8,%9}, {%0,%1,%2,%3};"
        : "+f"(d[0]), "+f"(d[1]), "+f"(d[2]), "+f"(d[3])
        : "r"(a[0]), "r"(a[1]), "r"(a[2]), "r"(a[3]), "r"(b0), "r"(b1));
}

__global__ void __launch_bounds__(256) mma_gemm_kernel(const float* __restrict__ src,
                                                       float* __restrict__ dst,
                                                       __half* __restrict__ dstH,
                                                       const __half* __restrict__ Wh,
                                                       float omb, float bscale,
                                                       float hscale) {
    extern __shared__ __half sh[];
    __half* As = sh;               // [128][MSTR]
    __half* Bs = sh + 128 * MSTR;  // [128][MSTR], [n][k]

    int tid = threadIdx.x;
    int r0 = blockIdx.x * 128;
    const __half* Axh = g_xxh + (size_t)r0 * HH;

    // stage A and B tiles (8 uint4 each per thread)
#pragma unroll
    for (int i = 0; i < 8; i++) {
        int idx = tid + i * 256;            // 0..2047
        int row = idx >> 4, q = idx & 15;
        *(uint4*)&As[row * MSTR + q * 8] = *(const uint4*)&Axh[row * HH + q * 8];
        *(uint4*)&Bs[row * MSTR + q * 8] = *(const uint4*)&Wh[row * HH + q * 8];
    }
    __syncthreads();

    int wid = tid >> 5, lane = tid & 31;
    int wm = wid >> 1, wn = wid & 1;
    int qid = lane >> 2, qt = lane & 3;

    float acc[2][8][4];
#pragma unroll
    for (int mt = 0; mt < 2; mt++)
#pragma unroll
        for (int nt = 0; nt < 8; nt++)
#pragma unroll
            for (int c = 0; c < 4; c++) acc[mt][nt][c] = 0.f;

#pragma unroll
    for (int ks = 0; ks < 8; ks++) {
        int kb = ks * 16;
        uint32_t a[2][4];
#pragma unroll
        for (int mt = 0; mt < 2; mt++) {
            int m = wm * 32 + mt * 16 + qid;
            a[mt][0] = *(const uint32_t*)&As[m * MSTR + kb + qt * 2];
            a[mt][1] = *(const uint32_t*)&As[(m + 8) * MSTR + kb + qt * 2];
            a[mt][2] = *(const uint32_t*)&As[m * MSTR + kb + qt * 2 + 8];
            a[mt][3] = *(const uint32_t*)&As[(m + 8) * MSTR + kb + qt * 2 + 8];
        }
#pragma unroll
        for (int nt = 0; nt < 8; nt++) {
            int n = wn * 64 + nt * 8 + qid;
            uint32_t b0 = *(const uint32_t*)&Bs[n * MSTR + kb + qt * 2];
            uint32_t b1 = *(const uint32_t*)&Bs[n * MSTR + kb + qt * 2 + 8];
            hmma(acc[0][nt], a[0], b0, b1);
            hmma(acc[1][nt], a[1], b0, b1);
        }
    }

    // epilogue: dst = src + relu(omb*xx + bscale*acc); mirror = dst*hscale
#pragma unroll
    for (int mt = 0; mt < 2; mt++) {
#pragma unroll
        for (int h = 0; h < 2; h++) {
            int row = r0 + wm * 32 + mt * 16 + qid + 8 * h;
            const float* xxr = &g_xx[(size_t)row * HH];
            const float* srr = &src[(size_t)row * HH];
            float* dsr = &dst[(size_t)row * HH];
            __half* dhr = &dstH[(size_t)row * HH];
#pragma unroll
            for (int nt = 0; nt < 8; nt++) {
                int col = wn * 64 + nt * 8 + qt * 2;
                float v0 = acc[mt][nt][2 * h + 0];
                float v1 = acc[mt][nt][2 * h + 1];
                float2 xx = *(const float2*)&xxr[col];
                float o0 = omb * xx.x + bscale * v0;
                float o1 = omb * xx.y + bscale * v1;
                float2 sv = *(const float2*)&srr[col];
                float d0 = sv.x + fmaxf(o0, 0.f);
                float d1 = sv.y + fmaxf(o1, 0.f);
                *(float2*)&dsr[col] = make_float2(d0, d1);
                __half2 hm = __floats2half2_rn(d0 * hscale, d1 * hscale);
                *(unsigned*)&dhr[col] = *(const unsigned*)&hm;
            }
        }
    }
}

// ---------------- output projection: out = xc @ W_out^T + b_out ----------------
__global__ void out_proj_kernel(const float* __restrict__ xc,
                                const float* __restrict__ Wout,
                                const float* __restrict__ bout,
                                float* __restrict__ out) {
    int gt = blockIdx.x * blockDim.x + threadIdx.x;
    int row = gt >> 5;
    int lane = threadIdx.x & 31;
    if (row >= NN) return;
    float4 v = ((const float4*)xc)[row * 32 + lane];
#pragma unroll
    for (int c = 0; c < 3; c++) {
        float4 w = *(const float4*)&Wout[c * HH + lane * 4];
        float s = v.x * w.x + v.y * w.y + v.z * w.z + v.w * w.w;
#pragma unroll
        for (int o = 16; o; o >>= 1) s += __shfl_down_sync(0xFFFFFFFFu, s, o);
        if (lane == 0) out[row * 3 + c] = s + bout[c];
    }
}

extern "C" void kernel_launch(void* const* d_in, const int* in_sizes, int n_in,
                              void* d_out, int out_size) {
    const float* x    = (const float*)d_in[0];
    const int*   er   = (const int*)d_in[1];
    const int*   ec   = (const int*)d_in[2];
    const float* ew   = (const float*)d_in[3];
    const float* Win  = (const float*)d_in[4];
    const float* bin  = (const float*)d_in[5];
    const float* Wout = (const float*)d_in[6];
    const float* bout = (const float*)d_in[7];
    const float* Wc   = (const float*)d_in[8];
    float* out = (float*)d_out;

    float*  bufA; cudaGetSymbolAddress((void**)&bufA, g_xca);
    float*  bufB; cudaGetSymbolAddress((void**)&bufB, g_xcb);
    __half* hbufA; cudaGetSymbolAddress((void**)&hbufA, g_xha);
    __half* hbufB; cudaGetSymbolAddress((void**)&hbufB, g_xhb);
    __half* wh;   cudaGetSymbolAddress((void**)&wh, g_wh);

    cudaFuncSetAttribute(mma_gemm_kernel,
                         cudaFuncAttributeMaxDynamicSharedMemorySize, SMEM_MMA);

    zero_cnt_kernel<<<(NN + 255) / 256, 256>>>();                    // launch 0
    whprep_kernel<<<(LL * HH * HH + 255) / 256, 256>>>(Wc);          // launch 1
    input_proj_kernel<<<NN / 32, 128>>>(x, Win, bin);                // launch 2
    scatter_ell_kernel<<<(EE + 255) / 256, 256>>>(er, ec, ew);       // launch 3

    for (int l = 0; l < LL; l++) {
        const float*  src  = (l & 1) ? bufB : bufA;
        float*        dst  = (l & 1) ? bufA : bufB;
        const __half* srcH = (l & 1) ? hbufB : hbufA;
        __half*       dstH = (l & 1) ? hbufA : hbufB;
        float beta = logf(0.5f / (float)(l + 1) + 1.0f);
        float invs = ldexpf(0.9f, 3 * l);            // 0.9 * 2^{3l}
        float sxx = ldexpf(1.0f, -3 * l);            // 2^{-3l}
        float bscale = beta * ldexpf(1.0f, 3 * l);   // beta * 2^{3l}
        float hscale = ldexpf(1.0f, -3 * (l + 1));   // 2^{-3(l+1)}
        spmm_kernel<<<(NN / 2 * 32 + 255) / 256, 256>>>(srcH, invs, sxx);
        mma_gemm_kernel<<<NP / 128, 256, SMEM_MMA>>>(src, dst, dstH,
                                                     wh + (size_t)l * HH * HH,
                                                     1.0f - beta, bscale, hscale);
    }

    out_proj_kernel<<<(NN * 32 + 255) / 256, 256>>>(bufA, Wout, bout, out);
}